// round 6
// baseline (speedup 1.0000x reference)
#include <cuda_runtime.h>

#define HID   51
#define GATES 204          // 4*HID
#define ROWS  205          // + fused FC row
#define SEQ   999
#define BATCH 4096
#define BT    8            // batch rows per block (4096/8 = 512 blocks, exact)
#define NBLK  (BATCH / BT) // 512
#define CHUNK 37           // 999 = 27*37
#define WPAD  52           // weight row stride (13 float4, conflict-free LDS.128)
#define GPAD  9            // gates row stride (gcd(9,32)=1 -> conflict-free STS.32)

// dynamic smem layout (floats)
#define W_OFF 0
#define G_OFF (ROWS * WPAD)              // 10660
#define H_OFF (G_OFF + GATES * GPAD)     // 12496
#define X_OFF (H_OFF + HID * BT)         // 12904
#define SMEM_FLOATS (X_OFF + BT * CHUNK) // 13200 -> 52800 bytes

typedef unsigned long long u64;

__device__ __forceinline__ u64 pack2(float a, float b) {
    u64 r; asm("mov.b64 %0,{%1,%2};" : "=l"(r) : "f"(a), "f"(b)); return r;
}
__device__ __forceinline__ void unpack2(float& a, float& b, u64 p) {
    asm("mov.b64 {%0,%1},%2;" : "=f"(a), "=f"(b) : "l"(p));
}
__device__ __forceinline__ u64 ffma2(u64 a, u64 b, u64 c) {
    u64 d; asm("fma.rn.f32x2 %0,%1,%2,%3;" : "=l"(d) : "l"(a), "l"(b), "l"(c)); return d;
}

__device__ __forceinline__ float sigf(float x) {
    return __fdividef(1.0f, 1.0f + __expf(-x));        // saturation-safe
}
__device__ __forceinline__ float tanh_(float x) {
    return __fdividef(2.0f, 1.0f + __expf(-2.0f * x)) - 1.0f;
}

__global__ __launch_bounds__(256, 4)
void lstm_persistent(const float* __restrict__ input,
                     const float* __restrict__ W_ih,
                     const float* __restrict__ W_hh,
                     const float* __restrict__ b_ih,
                     const float* __restrict__ b_hh,
                     const float* __restrict__ W_fc,
                     const float* __restrict__ b_fc,
                     float* __restrict__ out)
{
    extern __shared__ float sm[];
    const int tid = threadIdx.x;
    const int b0  = blockIdx.x * BT;                   // BATCH%BT==0 -> no tail

    // ---- init: weights -> SMEM (row 204 = FC), pads zeroed; h zeroed ----
    for (int e = tid; e < ROWS * WPAD; e += 256) {
        int r = e / WPAD, j = e - r * WPAD;
        float w = 0.0f;
        if (j < HID) w = (r < GATES) ? W_hh[r * HID + j] : W_fc[j];
        sm[W_OFF + e] = w;
    }
    for (int e = tid; e < HID * BT; e += 256) sm[H_OFF + e] = 0.0f;

    float bias = 0.0f, wih = 0.0f;
    if (tid < GATES)       { bias = b_ih[tid] + b_hh[tid]; wih = W_ih[tid]; }
    else if (tid == GATES) { bias = b_fc[0]; }

    // elementwise mapping: e = tid (+256); b = e&7, k = e>>3 ; 408 = 51*8 elems
    const int e0b = tid & 7, e0k = tid >> 3;           // e0k <= 31 < 51, always active
    const int e1b = e0b,     e1k = e0k + 32;           // active iff tid < 152
    float creg0 = 0.0f, creg1 = 0.0f;

    const float* wrow = sm + W_OFF + tid * WPAD;       // deref'd only for tid < ROWS
    const bool is_gate = (tid < GATES);
    const bool is_row  = (tid < ROWS);

    for (int t = 0; t <= SEQ; ++t) {
        if (t < SEQ && (t % CHUNK) == 0) {             // stage input chunk
            for (int e = tid; e < BT * CHUNK; e += 256) {
                int b = e / CHUNK, tc = e - b * CHUNK;
                sm[X_OFF + e] = input[(size_t)(b0 + b) * SEQ + (t + tc)];
            }
        }
        __syncthreads();   // A: h(t-1), x, (W on t=0) ready

        // ---- GEMM: rows 0..203 -> gates_t ; row 204 -> y_{t-1} ----
        if (is_row && (is_gate ? (t < SEQ) : (t > 0))) {
            const int tc = t % CHUNK;
            float a[BT];
            #pragma unroll
            for (int b = 0; b < BT; b++)
                a[b] = fmaf(wih, sm[X_OFF + b * CHUNK + tc], bias);  // wih==0 for FC
            u64 acc0 = pack2(a[0], a[1]);
            u64 acc1 = pack2(a[2], a[3]);
            u64 acc2 = pack2(a[4], a[5]);
            u64 acc3 = pack2(a[6], a[7]);

            #pragma unroll
            for (int q = 0; q < 13; q++) {
                float4 wq = *reinterpret_cast<const float4*>(wrow + 4 * q);
                #pragma unroll
                for (int s = 0; s < 4; s++) {
                    const int k = 4 * q + s;
                    if (k < HID) {
                        float w = (s == 0) ? wq.x : (s == 1) ? wq.y
                                 : (s == 2) ? wq.z : wq.w;
                        u64 wp = pack2(w, w);
                        const ulonglong2* hr =
                            reinterpret_cast<const ulonglong2*>(sm + H_OFF + k * BT);
                        ulonglong2 hlo = hr[0];        // b 0..3 (broadcast LDS.128)
                        ulonglong2 hhi = hr[1];        // b 4..7
                        acc0 = ffma2(hlo.x, wp, acc0);
                        acc1 = ffma2(hlo.y, wp, acc1);
                        acc2 = ffma2(hhi.x, wp, acc2);
                        acc3 = ffma2(hhi.y, wp, acc3);
                    }
                }
            }
            float o[BT];
            unpack2(o[0], o[1], acc0);
            unpack2(o[2], o[3], acc1);
            unpack2(o[4], o[5], acc2);
            unpack2(o[6], o[7], acc3);
            if (is_gate) {
                #pragma unroll
                for (int b = 0; b < BT; b++)
                    sm[G_OFF + tid * GPAD + b] = o[b]; // stride 9: conflict-free
            } else {
                #pragma unroll
                for (int b = 0; b < BT; b++)
                    out[(size_t)(b0 + b) * SEQ + (t - 1)] = o[b];
            }
        }
        __syncthreads();   // B: gates ready; GEMM done reading h(t-1)

        // ---- elementwise cell update -> h(t) ----
        if (t < SEQ) {
            {
                float gi = sm[G_OFF + (e0k          ) * GPAD + e0b];
                float gf = sm[G_OFF + (e0k +     HID) * GPAD + e0b];
                float gg = sm[G_OFF + (e0k + 2 * HID) * GPAD + e0b];
                float go = sm[G_OFF + (e0k + 3 * HID) * GPAD + e0b];
                float c  = sigf(gf) * creg0 + sigf(gi) * tanh_(gg);
                creg0 = c;
                sm[H_OFF + e0k * BT + e0b] = sigf(go) * tanh_(c);
            }
            if (tid < 152) {
                float gi = sm[G_OFF + (e1k          ) * GPAD + e1b];
                float gf = sm[G_OFF + (e1k +     HID) * GPAD + e1b];
                float gg = sm[G_OFF + (e1k + 2 * HID) * GPAD + e1b];
                float go = sm[G_OFF + (e1k + 3 * HID) * GPAD + e1b];
                float c  = sigf(gf) * creg1 + sigf(gi) * tanh_(gg);
                creg1 = c;
                sm[H_OFF + e1k * BT + e1b] = sigf(go) * tanh_(c);
            }
        }
    }
}

extern "C" void kernel_launch(void* const* d_in, const int* in_sizes, int n_in,
                              void* d_out, int out_size) {
    const float* input = (const float*)d_in[0];
    const float* W_ih  = (const float*)d_in[1];
    const float* W_hh  = (const float*)d_in[2];
    const float* b_ih  = (const float*)d_in[3];
    const float* b_hh  = (const float*)d_in[4];
    const float* W_fc  = (const float*)d_in[5];
    const float* b_fc  = (const float*)d_in[6];

    cudaFuncSetAttribute(lstm_persistent,
                         cudaFuncAttributeMaxDynamicSharedMemorySize,
                         SMEM_FLOATS * (int)sizeof(float));
    lstm_persistent<<<NBLK, 256, SMEM_FLOATS * sizeof(float)>>>(
        input, W_ih, W_hh, b_ih, b_hh, W_fc, b_fc, (float*)d_out);
}